// round 14
// baseline (speedup 1.0000x reference)
#include <cuda_runtime.h>
#include <cstdint>

// ---------------------------------------------------------------------------
// out = scale * (K - 2*mismatch), scale = 2^rint(clip(shift,-8,0))
// x [4,2048,4096] -> M=8192, K=4096 ; weight [16384,4096] -> N=16384
// Bitboard popcount GEMM. alu-pipe bound: XOR+POPC+0.25 add = 2.25 alu/word.
// Round 13: occupancy 2->3 CTAs/SM (smaller stages + reg diet) to close the
// ~30% issue-efficiency gap.
// ---------------------------------------------------------------------------
constexpr int K_DIM = 4096;
constexpr int KW    = K_DIM / 32;      // 128 words/row
constexpr int M_DIM = 8192;
constexpr int N_DIM = 16384;

constexpr int BM = 64;
constexpr int BN = 128;
constexpr int BKW = 16;                // words per stage chunk (64B of K)
constexpr int NKI = KW / BKW;          // 8 outer iterations
constexpr int ROW_B = 80;              // smem row stride bytes (64B + 16 pad)
constexpr int A_ST = BM * ROW_B;       // 5120
constexpr int B_ST = BN * ROW_B;       // 10240
constexpr int ST   = A_ST + B_ST;      // 15360
constexpr int SMEM_TOTAL = 2 * ST;     // 30720 (double buffered)

__device__ __align__(16) uint32_t g_Aw[(size_t)M_DIM * KW];  // 4 MB
__device__ __align__(16) uint32_t g_Bw[(size_t)N_DIM * KW];  // 8 MB

// ---------------------------------------------------------------------------
// Pack: one thread builds one 32-bit sign word from 32 consecutive floats.
// ---------------------------------------------------------------------------
__global__ void __launch_bounds__(256) pack_x_kernel(const float* __restrict__ x) {
    const size_t idx = (size_t)blockIdx.x * 256 + threadIdx.x;     // word index
    const float4* s = reinterpret_cast<const float4*>(x + (idx << 5));
    uint32_t w = 0;
#pragma unroll
    for (int q = 0; q < 8; q++) {
        float4 v = s[q];
        w |= (uint32_t)(v.x >= 0.0f) << (q * 4 + 0);
        w |= (uint32_t)(v.y >= 0.0f) << (q * 4 + 1);
        w |= (uint32_t)(v.z >= 0.0f) << (q * 4 + 2);
        w |= (uint32_t)(v.w >= 0.0f) << (q * 4 + 3);
    }
    g_Aw[idx] = w;
}

__global__ void __launch_bounds__(256) pack_w_kernel(const float* __restrict__ wgt,
                                                     const float* __restrict__ th) {
    const size_t idx = (size_t)blockIdx.x * 256 + threadIdx.x;
    const float thr = th[idx >> 7];                 // row = idx / KW
    const float4* s = reinterpret_cast<const float4*>(wgt + (idx << 5));
    uint32_t w = 0;
#pragma unroll
    for (int q = 0; q < 8; q++) {
        float4 v = s[q];
        w |= (uint32_t)(v.x - thr >= 0.0f) << (q * 4 + 0);
        w |= (uint32_t)(v.y - thr >= 0.0f) << (q * 4 + 1);
        w |= (uint32_t)(v.z - thr >= 0.0f) << (q * 4 + 2);
        w |= (uint32_t)(v.w - thr >= 0.0f) << (q * 4 + 3);
    }
    g_Bw[idx] = w;
}

// ---------------------------------------------------------------------------
// helpers
// ---------------------------------------------------------------------------
__device__ __forceinline__ uint32_t smem_u32(const void* p) {
    uint32_t a;
    asm("{ .reg .u64 t; cvta.to.shared.u64 t, %1; cvt.u32.u64 %0, t; }"
        : "=r"(a) : "l"(p));
    return a;
}
__device__ __forceinline__ void cp_async16(uint32_t dst, const void* src) {
    asm volatile("cp.async.ca.shared.global [%0], [%1], 16;"
                 :: "r"(dst), "l"(src) : "memory");
}
__device__ __forceinline__ void cp_commit() {
    asm volatile("cp.async.commit_group;" ::: "memory");
}
template <int N>
__device__ __forceinline__ void cp_wait() {
    asm volatile("cp.async.wait_group %0;" :: "n"(N) : "memory");
}

// 4-word xor+popc: 4 XOR + 4 POPC + 2 three-input adds (ptxas alternates the
// dependent add chain IADD3(alu) <-> IMAD(fma), so ~1 alu add per 8 words).
__device__ __forceinline__ void dot4(const uint32_t a[4], const uint32_t b[4],
                                     int& acc) {
    int p0 = __popc(a[0] ^ b[0]);
    int p1 = __popc(a[1] ^ b[1]);
    acc += p0 + p1;
    int p2 = __popc(a[2] ^ b[2]);
    int p3 = __popc(a[3] ^ b[3]);
    acc += p2 + p3;
}

// ---------------------------------------------------------------------------
// GEMM: CTA tile 64(m) x 128(n), 256 threads = 32(tx,n) x 8(ty,m),
// thread tile 8m x 4n, 3 CTAs/SM. B smem j-major (row = j*32+tx): bv LDS.128
// lanes stride 80B -> starting banks {0,20,8,28,16,4,24,12} per 8-lane phase,
// conflict-free. av loads warp-uniform broadcast. Layout verified rel_err=0.
// ---------------------------------------------------------------------------
__global__ void __launch_bounds__(256, 3)
bgemm_kernel(const float* __restrict__ shift, float* __restrict__ out) {
    extern __shared__ char smem[];
    const uint32_t sbase = smem_u32(smem);

    const int tid = threadIdx.x;
    const int tx = tid & 31;          // n group
    const int ty = tid >> 5;          // m group == warp id
    const int m0 = blockIdx.y * BM;
    const int n0 = blockIdx.x * BN;

    int acc[8][4];
#pragma unroll
    for (int i = 0; i < 8; i++)
#pragma unroll
        for (int j = 0; j < 4; j++) acc[i][j] = 0;

    // stage loader: 256 A-chunks + 512 B-chunks of 16B = 3 per thread
    auto load_stage = [&](int kk, int s) {
        const uint32_t sA = sbase + s * ST;
        const uint32_t sB = sA + A_ST;
        const int kw0 = kk * BKW;
        {   // A: c in [0,256)
            const int c = tid;
            const int row = c >> 2, ci = c & 3;
            cp_async16(sA + row * ROW_B + ci * 16,
                       g_Aw + (size_t)(m0 + row) * KW + kw0 + ci * 4);
        }
#pragma unroll
        for (int q = 0; q < 2; q++) {   // B: bc in [0,512)
            const int bc = tid + 256 * q;
            const int rs = bc >> 2, ci = bc & 3;
            const int j = rs >> 5, t2 = rs & 31;
            const int gn = n0 + t2 * 4 + j;
            cp_async16(sB + rs * ROW_B + ci * 16,
                       g_Bw + (size_t)gn * KW + kw0 + ci * 4);
        }
        cp_commit();
    };

    auto compute = [&](int s) {
        const char* cA = smem + s * ST;
        const char* cB = cA + A_ST;
#pragma unroll
        for (int sub = 0; sub < 4; sub++) {          // 4 x 4-word sub-chunks
            uint32_t bv[4][4];
#pragma unroll
            for (int j = 0; j < 4; j++) {
                const char* p = cB + (j * 32 + tx) * ROW_B + sub * 16;
                uint4 v = *reinterpret_cast<const uint4*>(p);
                bv[j][0] = v.x; bv[j][1] = v.y; bv[j][2] = v.z; bv[j][3] = v.w;
            }
#pragma unroll
            for (int i = 0; i < 8; i++) {
                const char* p = cA + (ty * 8 + i) * ROW_B + sub * 16;
                uint4 v = *reinterpret_cast<const uint4*>(p);
                uint32_t av[4] = {v.x, v.y, v.z, v.w};
#pragma unroll
                for (int j = 0; j < 4; j++) dot4(av, bv[j], acc[i][j]);
            }
        }
    };

    load_stage(0, 0);
#pragma unroll
    for (int kk = 0; kk < NKI; kk++) {
        if (kk + 1 < NKI) {
            load_stage(kk + 1, (kk + 1) & 1);
            cp_wait<1>();
        } else {
            cp_wait<0>();
        }
        __syncthreads();
        compute(kk & 1);
        __syncthreads();
    }

    const float sp = *shift;
    const float scale = exp2f(rintf(fminf(fmaxf(sp, -8.0f), 0.0f)));

#pragma unroll
    for (int i = 0; i < 8; i++) {
        const size_t row = (size_t)(m0 + ty * 8 + i);
        float4 v;
        v.x = scale * (float)(K_DIM - 2 * acc[i][0]);
        v.y = scale * (float)(K_DIM - 2 * acc[i][1]);
        v.z = scale * (float)(K_DIM - 2 * acc[i][2]);
        v.w = scale * (float)(K_DIM - 2 * acc[i][3]);
        *reinterpret_cast<float4*>(out + row * N_DIM + n0 + tx * 4) = v;
    }
}

// ---------------------------------------------------------------------------
// Launch
// ---------------------------------------------------------------------------
extern "C" void kernel_launch(void* const* d_in, const int* in_sizes, int n_in,
                              void* d_out, int out_size) {
    const float* x     = (const float*)d_in[0];
    const float* w     = (const float*)d_in[1];
    const float* th    = (const float*)d_in[2];
    const float* shift = (const float*)d_in[3];
    float* out = (float*)d_out;

    pack_x_kernel<<<(M_DIM * KW) / 256, 256>>>(x);
    pack_w_kernel<<<(N_DIM * KW) / 256, 256>>>(w, th);

    cudaFuncSetAttribute(bgemm_kernel, cudaFuncAttributeMaxDynamicSharedMemorySize, SMEM_TOTAL);
    dim3 grid(N_DIM / BN, M_DIM / BM);   // (128, 128)
    bgemm_kernel<<<grid, 256, SMEM_TOTAL>>>(shift, out);

    (void)in_sizes; (void)n_in; (void)out_size;
}